// round 10
// baseline (speedup 1.0000x reference)
#include <cuda_runtime.h>
#include <cuda_fp16.h>
#include <stdint.h>

// ============================================================================
// FusedNeRF on GB300 (sm_103a via compute_103 PTX -> no tcgen05; use classic
// warp-level mma.sync HMMA). Fully fused 9-layer MLP, fp32 accumulation,
// 2-term fp16 split of both operands (3 MMAs per k-tile/n-tile pair).
//
// CTA = 128 rows x 256 threads. Warp w owns rows w*16..w*16+15, all 128 cols.
// Activations live in registers as next-layer A-fragments (D->A layout is
// thread-congruent). Weights are prepared as the exact per-lane B-fragment
// byte image by a prep kernel; per-layer fetch = byte-identity cp.async into
// double-buffered SMEM.
// ============================================================================

// ---- SMEM layout (byte offsets in dynamic smem) ----
#define OFF_WA   0          // 98304  (odd layers 1,3,5,7; also x staging)
#define OFF_WB   98304      // 69632  (even layers 0,2,4,6,8)
#define OFF_P_HI 167936     // 16384  pos A-frags hi (8 warps x 4 kt x 32 x 16B)
#define OFF_P_LO 184320     // 16384
#define OFF_V_HI 200704     // 8192   view A-frags hi (8 warps x 2 kt x 32 x 16B)
#define OFF_V_LO 208896     // 8192
#define SMEM_ALLOC 217088

// Prepared weight image: per layer [hi frags | lo frags]; frag (kt,nt,lane)
// is 8 bytes at ((kt*NT+nt)*32+lane)*8.
__device__ __align__(1024) unsigned char g_wbuf[548864];

// Layer tables (prep kernel): NT (n8 tiles)
__constant__ int p_NT[9]   = {16,16,16,16,16,16,17,16,1};
__constant__ int p_CNT[9]  = {2048,4096,4096,6144,4096,4096,4352,5120,256}; // KT*NT*32
__constant__ int p_BASE[9] = {0,32768,98304,163840,262144,327680,393216,462848,544768};
__constant__ int p_HALF[9] = {16384,32768,32768,49152,32768,32768,34816,40960,2048};

// ---------------------------------------------------------------------------
// helpers
// ---------------------------------------------------------------------------
__device__ __forceinline__ uint32_t smem_u32(const void* p) {
    uint32_t a;
    asm("{ .reg .u64 t; cvta.to.shared.u64 t, %1; cvt.u32.u64 %0, t; }" : "=r"(a) : "l"(p));
    return a;
}

__device__ __forceinline__ void lds64(uint32_t a, uint32_t& x, uint32_t& y) {
    asm volatile("ld.shared.v2.b32 {%0,%1}, [%2];" : "=r"(x), "=r"(y) : "r"(a));
}

__device__ __forceinline__ void lds128(uint32_t a, uint32_t (&r)[4]) {
    asm volatile("ld.shared.v4.b32 {%0,%1,%2,%3}, [%4];"
                 : "=r"(r[0]), "=r"(r[1]), "=r"(r[2]), "=r"(r[3]) : "r"(a));
}

__device__ __forceinline__ void sts128(uint32_t a, uint32_t v0, uint32_t v1,
                                       uint32_t v2, uint32_t v3) {
    asm volatile("st.shared.v4.b32 [%0], {%1,%2,%3,%4};"
                 :: "r"(a), "r"(v0), "r"(v1), "r"(v2), "r"(v3) : "memory");
}

__device__ __forceinline__ void cp16(uint32_t dst, const void* src) {
    asm volatile("{ .reg .u64 g; cvta.to.global.u64 g, %1;"
                 " cp.async.cg.shared.global [%0], [g], 16; }"
                 :: "r"(dst), "l"(src) : "memory");
}

#define CP_COMMIT() asm volatile("cp.async.commit_group;" ::: "memory")
#define CP_WAIT(n)  asm volatile("cp.async.wait_group %0;" :: "n"(n) : "memory")

__device__ __forceinline__ void mma16816(float (&d)[4], const uint32_t (&a)[4],
                                         uint32_t b0, uint32_t b1) {
    asm volatile(
        "mma.sync.aligned.m16n8k16.row.col.f32.f16.f16.f32 "
        "{%0,%1,%2,%3}, {%4,%5,%6,%7}, {%8,%9}, {%0,%1,%2,%3};"
        : "+f"(d[0]), "+f"(d[1]), "+f"(d[2]), "+f"(d[3])
        : "r"(a[0]), "r"(a[1]), "r"(a[2]), "r"(a[3]), "r"(b0), "r"(b1));
}

// relu(optional) + 2-term fp16 split of a value pair, packed f16x2
__device__ __forceinline__ void split2(float v0, float v1, bool relu,
                                       uint32_t& hi, uint32_t& lo) {
    if (relu) { v0 = fmaxf(v0, 0.f); v1 = fmaxf(v1, 0.f); }
    __half h0 = __float2half_rn(v0);
    __half h1 = __float2half_rn(v1);
    __half e0 = __float2half_rn(v0 - __half2float(h0));
    __half e1 = __float2half_rn(v1 - __half2float(h1));
    hi = (uint32_t)__half_as_ushort(h0) | ((uint32_t)__half_as_ushort(h1) << 16);
    lo = (uint32_t)__half_as_ushort(e0) | ((uint32_t)__half_as_ushort(e1) << 16);
}

// ---------------------------------------------------------------------------
// Prep kernel: write per-lane B fragments (hi and lo fp16 split), with concat
// zero-padding and the d2_W3 column permutation baked in.
// One thread per (layer, kt, nt, lane). Grid = 134 x 256 = 34304 threads.
// ---------------------------------------------------------------------------
struct WPtrs { const float* w[9]; };

__device__ __forceinline__ float wfetch(const WPtrs& wp, int l, int k, int n) {
    int ks = -1, ns = -1, nc = 128;
    switch (l) {
        case 0: ks = (k < 63) ? k : -1; ns = n; break;                       // d1_W0 63x128
        case 1: case 2: ks = k; ns = n; break;                               // 128x128
        case 3: ks = (k < 63) ? k : ((k >= 64) ? (k - 1) : -1); ns = n; break; // d2_W0 191x128
        case 4: case 5: ks = k; ns = n; break;
        case 6: ks = k; ns = (n < 128) ? (n + 1) : ((n == 128) ? 0 : -1); nc = 129; break; // d2_W3
        case 7: ks = (k < 27) ? k : ((k >= 32) ? (k - 5) : -1); ns = n; break; // c_W0 155x128
        case 8: ks = k; ns = (n < 3) ? n : -1; nc = 3; break;                // c_W1 128x3
    }
    if (ks < 0 || ns < 0) return 0.f;
    return wp.w[l][(size_t)ks * nc + ns];
}

__global__ void nerf_prep(WPtrs wp) {
    int gid = blockIdx.x * blockDim.x + threadIdx.x;
    int l = 0, rem = gid;
    while (l < 9 && rem >= p_CNT[l]) { rem -= p_CNT[l]; l++; }
    if (l >= 9) return;
    int NT = p_NT[l];
    int nt32 = NT * 32;
    int kt = rem / nt32;
    int r2 = rem - kt * nt32;
    int nt = r2 >> 5;
    int lane = r2 & 31;
    int g = lane >> 2, tig = lane & 3;

    int n  = nt * 8 + g;
    int k0 = kt * 16 + tig * 2;

    // B frag: b0 = {W[k0][n], W[k0+1][n]}, b1 = {W[k0+8][n], W[k0+9][n]}
    float v0 = wfetch(wp, l, k0,     n);
    float v1 = wfetch(wp, l, k0 + 1, n);
    float v2 = wfetch(wp, l, k0 + 8, n);
    float v3 = wfetch(wp, l, k0 + 9, n);

    uint32_t h0, l0, h1, l1;
    split2(v0, v1, false, h0, l0);
    split2(v2, v3, false, h1, l1);

    size_t off = ((size_t)(kt * NT + nt) * 32 + lane) * 8;
    *(uint2*)(g_wbuf + p_BASE[l] + off)             = make_uint2(h0, h1);
    *(uint2*)(g_wbuf + p_BASE[l] + p_HALF[l] + off) = make_uint2(l0, l1);
}

// ---------------------------------------------------------------------------
// One layer: KT k16-tiles x NT n8-tiles, 3 split MMAs each; convert D->A frags.
// MODE: 0 = act regs only; 1 = pos frags only (L0); 2 = pos(4kt)+act (L3);
//       3 = view(2kt)+act (L7).
// ---------------------------------------------------------------------------
template <int KT, int NT, int MODE, bool RELU, bool DENS>
__device__ __forceinline__ void run_layer(
    uint32_t wb, uint32_t hoff, uint32_t pvhi, uint32_t pvlo,
    uint32_t (&aH)[8][4], uint32_t (&aL)[8][4],
    float& d0, float& d1, float (&fin)[4], int lane)
{
    float acc[NT][4];
    #pragma unroll
    for (int i = 0; i < NT; i++) {
        acc[i][0] = 0.f; acc[i][1] = 0.f; acc[i][2] = 0.f; acc[i][3] = 0.f;
    }

    #pragma unroll
    for (int kt = 0; kt < KT; kt++) {
        uint32_t ah[4], al[4];
        if (MODE == 1) {
            lds128(pvhi + (kt * 32 + lane) * 16, ah);
            lds128(pvlo + (kt * 32 + lane) * 16, al);
        } else if (MODE == 2) {
            if (kt < 4) {
                lds128(pvhi + (kt * 32 + lane) * 16, ah);
                lds128(pvlo + (kt * 32 + lane) * 16, al);
            } else {
                int ki = (kt >= 4) ? (kt - 4) : 0;
                #pragma unroll
                for (int j = 0; j < 4; j++) { ah[j] = aH[ki][j]; al[j] = aL[ki][j]; }
            }
        } else if (MODE == 3) {
            if (kt < 2) {
                lds128(pvhi + (kt * 32 + lane) * 16, ah);
                lds128(pvlo + (kt * 32 + lane) * 16, al);
            } else {
                int ki = (kt >= 2) ? (kt - 2) : 0;
                #pragma unroll
                for (int j = 0; j < 4; j++) { ah[j] = aH[ki][j]; al[j] = aL[ki][j]; }
            }
        } else {
            #pragma unroll
            for (int j = 0; j < 4; j++) { ah[j] = aH[kt][j]; al[j] = aL[kt][j]; }
        }

        #pragma unroll
        for (int nt = 0; nt < NT; nt++) {
            uint32_t off = (uint32_t)((kt * NT + nt) * 256) + (uint32_t)lane * 8;
            uint32_t b0, b1, c0, c1;
            lds64(wb + off, b0, b1);
            lds64(wb + hoff + off, c0, c1);
            mma16816(acc[nt], ah, b0, b1);   // Ah * Wh
            mma16816(acc[nt], ah, c0, c1);   // Ah * Wl
            mma16816(acc[nt], al, b0, b1);   // Al * Wh
        }
    }

    // D -> next-layer A fragments (register-local; tiles (2k,2k+1) -> kt k)
    if constexpr (NT >= 16) {
        #pragma unroll
        for (int k2 = 0; k2 < 8; k2++) {
            split2(acc[2*k2][0],   acc[2*k2][1],   RELU, aH[k2][0], aL[k2][0]);
            split2(acc[2*k2][2],   acc[2*k2][3],   RELU, aH[k2][1], aL[k2][1]);
            split2(acc[2*k2+1][0], acc[2*k2+1][1], RELU, aH[k2][2], aL[k2][2]);
            split2(acc[2*k2+1][2], acc[2*k2+1][3], RELU, aH[k2][3], aL[k2][3]);
        }
    }
    if constexpr (DENS) {         // tile 16, col 128 (source density col 0) @ tig==0
        d0 = acc[NT - 1][0];      // row g
        d1 = acc[NT - 1][2];      // row g+8
    }
    if constexpr (NT == 1) {
        fin[0] = acc[0][0]; fin[1] = acc[0][1]; fin[2] = acc[0][2]; fin[3] = acc[0][3];
    }
}

// ---------------------------------------------------------------------------
// Main fused kernel
// ---------------------------------------------------------------------------
__device__ __forceinline__ void prefetch(uint32_t dst, const unsigned char* src,
                                         int bytes, int tid) {
    for (int i = tid * 16; i < bytes; i += 256 * 16) cp16(dst + i, src + i);
    CP_COMMIT();
}

__global__ void __launch_bounds__(256, 1)
nerf_main(const float* __restrict__ x, float* __restrict__ out) {
    extern __shared__ __align__(16) unsigned char smem_raw[];
    uint32_t sb = smem_u32(smem_raw);
    int tid  = threadIdx.x;
    int lane = tid & 31;
    int warp = tid >> 5;
    int g = lane >> 2, tig = lane & 3;

    uint32_t WA = sb + OFF_WA, WB = sb + OFF_WB;
    uint32_t Ph = sb + OFF_P_HI + warp * (4 * 512);
    uint32_t Pl = sb + OFF_P_LO + warp * (4 * 512);
    uint32_t Vh = sb + OFF_V_HI + warp * (2 * 512);
    uint32_t Vl = sb + OFF_V_LO + warp * (2 * 512);

    // G0: layer-0 weights -> WB
    prefetch(WB, g_wbuf + 0, 32768, tid);

    // stage x tile (128 rows x 90 f32) into WA region
    float* xs = reinterpret_cast<float*>(smem_raw + OFF_WA);
    {
        const float* xt = x + (size_t)blockIdx.x * 128 * 90;
        for (int i = tid; i < 128 * 90; i += 256) xs[i] = xt[i];
    }
    __syncthreads();

    // build pos (4 kt, 63 cols) and view (2 kt, 27 cols) A-fragments (hi/lo)
    {
        int r0 = warp * 16 + g, r1 = r0 + 8;
        #pragma unroll
        for (int kt = 0; kt < 4; kt++) {
            int c0 = kt * 16 + tig * 2;
            float f[8];
            #pragma unroll
            for (int j = 0; j < 4; j++) {
                int c = c0 + ((j < 2) ? j : (j + 6));   // c0, c0+1, c0+8, c0+9
                f[j]     = (c < 63) ? xs[r0 * 90 + c] : 0.f;
                f[4 + j] = (c < 63) ? xs[r1 * 90 + c] : 0.f;
            }
            uint32_t h[4], lo[4];
            split2(f[0], f[1], false, h[0], lo[0]);
            split2(f[4], f[5], false, h[1], lo[1]);
            split2(f[2], f[3], false, h[2], lo[2]);
            split2(f[6], f[7], false, h[3], lo[3]);
            sts128(Ph + (kt * 32 + lane) * 16, h[0], h[1], h[2], h[3]);
            sts128(Pl + (kt * 32 + lane) * 16, lo[0], lo[1], lo[2], lo[3]);
        }
        #pragma unroll
        for (int kt = 0; kt < 2; kt++) {
            int c0 = kt * 16 + tig * 2;
            float f[8];
            #pragma unroll
            for (int j = 0; j < 4; j++) {
                int c = c0 + ((j < 2) ? j : (j + 6));
                f[j]     = (c < 27) ? xs[r0 * 90 + 63 + c] : 0.f;
                f[4 + j] = (c < 27) ? xs[r1 * 90 + 63 + c] : 0.f;
            }
            uint32_t h[4], lo[4];
            split2(f[0], f[1], false, h[0], lo[0]);
            split2(f[4], f[5], false, h[1], lo[1]);
            split2(f[2], f[3], false, h[2], lo[2]);
            split2(f[6], f[7], false, h[3], lo[3]);
            sts128(Vh + (kt * 32 + lane) * 16, h[0], h[1], h[2], h[3]);
            sts128(Vl + (kt * 32 + lane) * 16, lo[0], lo[1], lo[2], lo[3]);
        }
    }

    uint32_t aH[8][4], aL[8][4];
    float d0 = 0.f, d1 = 0.f;
    float fin[4] = {0.f, 0.f, 0.f, 0.f};

    // ---- layer 0 (pos @ d1_W0) ----
    __syncthreads();                                   // xs reads done
    prefetch(WA, g_wbuf + 32768, 65536, tid);          // L1
    CP_WAIT(1); __syncthreads();
    run_layer<4, 16, 1, true, false>(WB, 16384, Ph, Pl, aH, aL, d0, d1, fin, lane);

    // ---- layer 1 ----
    __syncthreads();
    prefetch(WB, g_wbuf + 98304, 65536, tid);          // L2
    CP_WAIT(1); __syncthreads();
    run_layer<8, 16, 0, true, false>(WA, 32768, 0, 0, aH, aL, d0, d1, fin, lane);

    // ---- layer 2 ----
    __syncthreads();
    prefetch(WA, g_wbuf + 163840, 98304, tid);         // L3
    CP_WAIT(1); __syncthreads();
    run_layer<8, 16, 0, true, false>(WB, 32768, 0, 0, aH, aL, d0, d1, fin, lane);

    // ---- layer 3 ([pos|part1] @ d2_W0) ----
    __syncthreads();
    prefetch(WB, g_wbuf + 262144, 65536, tid);         // L4
    CP_WAIT(1); __syncthreads();
    run_layer<12, 16, 2, true, false>(WA, 49152, Ph, Pl, aH, aL, d0, d1, fin, lane);

    // ---- layer 4 ----
    __syncthreads();
    prefetch(WA, g_wbuf + 327680, 65536, tid);         // L5
    CP_WAIT(1); __syncthreads();
    run_layer<8, 16, 0, true, false>(WB, 32768, 0, 0, aH, aL, d0, d1, fin, lane);

    // ---- layer 5 ----
    __syncthreads();
    prefetch(WB, g_wbuf + 393216, 69632, tid);         // L6
    CP_WAIT(1); __syncthreads();
    run_layer<8, 16, 0, true, false>(WA, 32768, 0, 0, aH, aL, d0, d1, fin, lane);

    // ---- layer 6 (d2_W3: feature cols 0..127 permuted, density col 128; no relu) ----
    __syncthreads();
    prefetch(WA, g_wbuf + 462848, 81920, tid);         // L7
    CP_WAIT(1); __syncthreads();
    run_layer<8, 17, 0, false, true>(WB, 34816, 0, 0, aH, aL, d0, d1, fin, lane);

    // ---- layer 7 ([view|feature] @ c_W0) ----
    __syncthreads();
    prefetch(WB, g_wbuf + 544768, 4096, tid);          // L8
    CP_WAIT(1); __syncthreads();
    run_layer<10, 16, 3, true, false>(WA, 40960, Vh, Vl, aH, aL, d0, d1, fin, lane);

    // ---- layer 8 (c_W1, no relu) ----
    __syncthreads();
    CP_WAIT(0); __syncthreads();
    run_layer<8, 1, 0, false, false>(WB, 2048, 0, 0, aH, aL, d0, d1, fin, lane);

    // ---- epilogue: gather rgb+density per row via per-warp smem scratch ----
    float* scr = reinterpret_cast<float*>(smem_raw + OFF_P_HI + warp * 256);
    __syncwarp();
    if (tig == 0) {
        scr[g * 4 + 0] = fin[0];          // r (col 0), row g
        scr[g * 4 + 1] = fin[1];          // g (col 1)
        scr[(g + 8) * 4 + 0] = fin[2];    // row g+8
        scr[(g + 8) * 4 + 1] = fin[3];
        scr[g * 4 + 3] = d0;              // density
        scr[(g + 8) * 4 + 3] = d1;
    } else if (tig == 1) {
        scr[g * 4 + 2] = fin[0];          // b (col 2), row g
        scr[(g + 8) * 4 + 2] = fin[2];    // row g+8
    }
    __syncwarp();
    if (lane < 16) {
        float4 o = *reinterpret_cast<float4*>(scr + lane * 4);
        reinterpret_cast<float4*>(out)[(size_t)blockIdx.x * 128 + warp * 16 + lane] = o;
    }
}

// ---------------------------------------------------------------------------
extern "C" void kernel_launch(void* const* d_in, const int* in_sizes, int n_in,
                              void* d_out, int out_size) {
    const float* x = (const float*)d_in[0];
    WPtrs wp;
    for (int i = 0; i < 9; i++) wp.w[i] = (const float*)d_in[1 + i];

    cudaFuncSetAttribute(nerf_main, cudaFuncAttributeMaxDynamicSharedMemorySize, SMEM_ALLOC);

    nerf_prep<<<134, 256>>>(wp);                  // 134*256 = 34304 frag threads
    nerf_main<<<8192, 256, SMEM_ALLOC>>>(x, (float*)d_out);
}

// round 12
// speedup vs baseline: 1.0140x; 1.0140x over previous
#include <cuda_runtime.h>
#include <cuda_fp16.h>
#include <stdint.h>

// ============================================================================
// FusedNeRF on GB300 (sm_103a, compute_103 PTX -> classic mma.sync HMMA).
// Fully fused 9-layer MLP, fp32 accumulation, 2-term fp16 split of both
// operands (3 MMAs per k/n tile).
//
// R11 restructure (evidence: tensor=58.3%, occ=12.5%, regs=255, 1 CTA/SM):
//  - Weights fetched per-warp via coalesced LDG.128 from the prepared image
//    (L1/L2-resident; hi+lo packed in one uint4) -> no SMEM weight buffers,
//    no cp.async, and NO inter-layer __syncthreads at all.
//  - Activation A-fragments live in warp-private SMEM planes (hi | lo),
//    cutting register pressure so __launch_bounds__(256,2) gives 2 CTAs/SM.
// ============================================================================

// ---- SMEM layout (per CTA, bytes) ----
#define S_ACT   0        // 65536: 8 warps x 8 kt x (512 hi + 512 lo); also x staging
#define S_POS   65536    // 32768: 8 warps x 4 kt x 1024
#define S_VIEW  98304    // 16384: 8 warps x 2 kt x 1024
#define SMEM_ALLOC 114688  // x2 CTAs = 229376 <= 232448 (227KB)

// Prepared weight image: frag (kt,nt,lane) = uint4{hi_b0,hi_b1,lo_b0,lo_b1}
// at BASE[l] + ((kt*NT+nt)*32+lane)*16.
__device__ __align__(1024) unsigned char g_wbuf[548864];

__constant__ int p_NT[9]   = {16,16,16,16,16,16,17,16,1};
__constant__ int p_CNT[9]  = {2048,4096,4096,6144,4096,4096,4352,5120,256}; // KT*NT*32
__constant__ int p_BASE[9] = {0,32768,98304,163840,262144,327680,393216,462848,544768};

// ---------------------------------------------------------------------------
// helpers
// ---------------------------------------------------------------------------
__device__ __forceinline__ uint32_t smem_u32(const void* p) {
    uint32_t a;
    asm("{ .reg .u64 t; cvta.to.shared.u64 t, %1; cvt.u32.u64 %0, t; }" : "=r"(a) : "l"(p));
    return a;
}

__device__ __forceinline__ void lds128(uint32_t a, uint32_t (&r)[4]) {
    asm volatile("ld.shared.v4.b32 {%0,%1,%2,%3}, [%4];"
                 : "=r"(r[0]), "=r"(r[1]), "=r"(r[2]), "=r"(r[3]) : "r"(a));
}

__device__ __forceinline__ void sts128(uint32_t a, uint32_t v0, uint32_t v1,
                                       uint32_t v2, uint32_t v3) {
    asm volatile("st.shared.v4.b32 [%0], {%1,%2,%3,%4};"
                 :: "r"(a), "r"(v0), "r"(v1), "r"(v2), "r"(v3) : "memory");
}

__device__ __forceinline__ void mma16816(float (&d)[4], const uint32_t (&a)[4],
                                         uint32_t b0, uint32_t b1) {
    asm volatile(
        "mma.sync.aligned.m16n8k16.row.col.f32.f16.f16.f32 "
        "{%0,%1,%2,%3}, {%4,%5,%6,%7}, {%8,%9}, {%0,%1,%2,%3};"
        : "+f"(d[0]), "+f"(d[1]), "+f"(d[2]), "+f"(d[3])
        : "r"(a[0]), "r"(a[1]), "r"(a[2]), "r"(a[3]), "r"(b0), "r"(b1));
}

// relu(optional) + 2-term fp16 split of a value pair, packed f16x2
__device__ __forceinline__ void split2(float v0, float v1, bool relu,
                                       uint32_t& hi, uint32_t& lo) {
    if (relu) { v0 = fmaxf(v0, 0.f); v1 = fmaxf(v1, 0.f); }
    __half h0 = __float2half_rn(v0);
    __half h1 = __float2half_rn(v1);
    __half e0 = __float2half_rn(v0 - __half2float(h0));
    __half e1 = __float2half_rn(v1 - __half2float(h1));
    hi = (uint32_t)__half_as_ushort(h0) | ((uint32_t)__half_as_ushort(h1) << 16);
    lo = (uint32_t)__half_as_ushort(e0) | ((uint32_t)__half_as_ushort(e1) << 16);
}

// ---------------------------------------------------------------------------
// Prep kernel: per-lane B fragments, hi+lo packed in one uint4, with concat
// zero-padding and the d2_W3 column permutation baked in.
// One thread per (layer, kt, nt, lane). Grid = 134 x 256.
// ---------------------------------------------------------------------------
struct WPtrs { const float* w[9]; };

__device__ __forceinline__ float wfetch(const WPtrs& wp, int l, int k, int n) {
    int ks = -1, ns = -1, nc = 128;
    switch (l) {
        case 0: ks = (k < 63) ? k : -1; ns = n; break;                       // d1_W0 63x128
        case 1: case 2: ks = k; ns = n; break;                               // 128x128
        case 3: ks = (k < 63) ? k : ((k >= 64) ? (k - 1) : -1); ns = n; break; // d2_W0 191x128
        case 4: case 5: ks = k; ns = n; break;
        case 6: ks = k; ns = (n < 128) ? (n + 1) : ((n == 128) ? 0 : -1); nc = 129; break; // d2_W3
        case 7: ks = (k < 27) ? k : ((k >= 32) ? (k - 5) : -1); ns = n; break; // c_W0 155x128
        case 8: ks = k; ns = (n < 3) ? n : -1; nc = 3; break;                // c_W1 128x3
    }
    if (ks < 0 || ns < 0) return 0.f;
    return wp.w[l][(size_t)ks * nc + ns];
}

__global__ void nerf_prep(WPtrs wp) {
    int gid = blockIdx.x * blockDim.x + threadIdx.x;
    int l = 0, rem = gid;
    while (l < 9 && rem >= p_CNT[l]) { rem -= p_CNT[l]; l++; }
    if (l >= 9) return;
    int NT = p_NT[l];
    int nt32 = NT * 32;
    int kt = rem / nt32;
    int r2 = rem - kt * nt32;
    int nt = r2 >> 5;
    int lane = r2 & 31;
    int g = lane >> 2, tig = lane & 3;

    int n  = nt * 8 + g;
    int k0 = kt * 16 + tig * 2;

    // B frag: b0 = {W[k0][n], W[k0+1][n]}, b1 = {W[k0+8][n], W[k0+9][n]}
    float v0 = wfetch(wp, l, k0,     n);
    float v1 = wfetch(wp, l, k0 + 1, n);
    float v2 = wfetch(wp, l, k0 + 8, n);
    float v3 = wfetch(wp, l, k0 + 9, n);

    uint32_t h0, l0, h1, l1;
    split2(v0, v1, false, h0, l0);
    split2(v2, v3, false, h1, l1);

    size_t off = ((size_t)(kt * NT + nt) * 32 + lane) * 16;
    *(uint4*)(g_wbuf + p_BASE[l] + off) = make_uint4(h0, h1, l0, l1);
}

// ---------------------------------------------------------------------------
// One layer: KT k16-tiles x NT n8-tiles, 3 split MMAs each.
// A-frags read from SMEM: kt < n1 -> a1 + kt*1024, else a2 + (kt-n1)*1024
// (hi plane at +0, lo plane at +512). If WRITE, epilogue converts D tiles
// (2k,2k+1) -> act frag kt k at dst (warp-private; no syncs needed).
// ---------------------------------------------------------------------------
template <int KT, int NT, bool RELU, bool DENS, bool WRITE>
__device__ __forceinline__ void run_layer(
    const uint4* __restrict__ w, uint32_t a1, int n1, uint32_t a2,
    uint32_t dst, float& d0, float& d1, float (&fin)[4], int lane)
{
    float acc[NT][4];
    #pragma unroll
    for (int i = 0; i < NT; i++) {
        acc[i][0] = 0.f; acc[i][1] = 0.f; acc[i][2] = 0.f; acc[i][3] = 0.f;
    }

    #pragma unroll
    for (int kt = 0; kt < KT; kt++) {
        uint32_t ab = (kt < n1) ? (a1 + (uint32_t)kt * 1024u)
                                : (a2 + (uint32_t)(kt - n1) * 1024u);
        uint32_t ah[4], al[4];
        lds128(ab + (uint32_t)lane * 16u, ah);
        lds128(ab + 512u + (uint32_t)lane * 16u, al);

        #pragma unroll
        for (int nt = 0; nt < NT; nt++) {
            uint4 wv = w[(uint32_t)(kt * NT + nt) * 32u + (uint32_t)lane]; // LDG.128
            mma16816(acc[nt], ah, wv.x, wv.y);   // Ah * Wh
            mma16816(acc[nt], ah, wv.z, wv.w);   // Ah * Wl
            mma16816(acc[nt], al, wv.x, wv.y);   // Al * Wh
        }
    }

    if constexpr (WRITE) {
        #pragma unroll
        for (int k2 = 0; k2 < 8; k2++) {
            uint32_t h[4], lo[4];
            split2(acc[2*k2][0],   acc[2*k2][1],   RELU, h[0], lo[0]);
            split2(acc[2*k2][2],   acc[2*k2][3],   RELU, h[1], lo[1]);
            split2(acc[2*k2+1][0], acc[2*k2+1][1], RELU, h[2], lo[2]);
            split2(acc[2*k2+1][2], acc[2*k2+1][3], RELU, h[3], lo[3]);
            uint32_t da = dst + (uint32_t)k2 * 1024u + (uint32_t)lane * 16u;
            sts128(da,        h[0],  h[1],  h[2],  h[3]);
            sts128(da + 512u, lo[0], lo[1], lo[2], lo[3]);
        }
    }
    if constexpr (DENS) {         // tile NT-1, col 128 (density) @ tig==0
        d0 = acc[NT - 1][0];      // row g
        d1 = acc[NT - 1][2];      // row g+8
    }
    if constexpr (NT == 1) {
        fin[0] = acc[0][0]; fin[1] = acc[0][1]; fin[2] = acc[0][2]; fin[3] = acc[0][3];
    }
}

// ---------------------------------------------------------------------------
// Main fused kernel: 1 CTA = 128 rows x 256 threads, 2 CTAs/SM.
// ---------------------------------------------------------------------------
__global__ void __launch_bounds__(256, 2)
nerf_main(const float* __restrict__ x, float* __restrict__ out) {
    extern __shared__ __align__(16) unsigned char smem_raw[];
    uint32_t sb = smem_u32(smem_raw);
    int tid  = threadIdx.x;
    int lane = tid & 31;
    int warp = tid >> 5;
    int g = lane >> 2, tig = lane & 3;

    uint32_t ACT  = sb + S_ACT  + (uint32_t)warp * 8192u;   // 8 kt slots
    uint32_t POS  = sb + S_POS  + (uint32_t)warp * 4096u;   // 4 kt slots
    uint32_t VIEW = sb + S_VIEW + (uint32_t)warp * 2048u;   // 2 kt slots

    // stage x tile (128 rows x 90 f32 = 45KB) into the ACT region (CTA-wide)
    float* xs = reinterpret_cast<float*>(smem_raw + S_ACT);
    {
        const float* xt = x + (size_t)blockIdx.x * 128 * 90;
        for (int i = tid; i < 128 * 90; i += 256) xs[i] = xt[i];
    }
    __syncthreads();

    // build pos (4 kt, 63 cols) and view (2 kt, 27 cols) A-fragments (hi|lo planes)
    {
        int r0 = warp * 16 + g, r1 = r0 + 8;
        #pragma unroll
        for (int kt = 0; kt < 4; kt++) {
            int c0 = kt * 16 + tig * 2;
            float f[8];
            #pragma unroll
            for (int j = 0; j < 4; j++) {
                int c = c0 + ((j < 2) ? j : (j + 6));   // c0, c0+1, c0+8, c0+9
                f[j]     = (c < 63) ? xs[r0 * 90 + c] : 0.f;
                f[4 + j] = (c < 63) ? xs[r1 * 90 + c] : 0.f;
            }
            uint32_t h[4], lo[4];
            split2(f[0], f[1], false, h[0], lo[0]);
            split2(f[4], f[5], false, h[1], lo[1]);
            split2(f[2], f[3], false, h[2], lo[2]);
            split2(f[6], f[7], false, h[3], lo[3]);
            uint32_t pa = POS + (uint32_t)kt * 1024u + (uint32_t)lane * 16u;
            sts128(pa,        h[0],  h[1],  h[2],  h[3]);
            sts128(pa + 512u, lo[0], lo[1], lo[2], lo[3]);
        }
        #pragma unroll
        for (int kt = 0; kt < 2; kt++) {
            int c0 = kt * 16 + tig * 2;
            float f[8];
            #pragma unroll
            for (int j = 0; j < 4; j++) {
                int c = c0 + ((j < 2) ? j : (j + 6));
                f[j]     = (c < 27) ? xs[r0 * 90 + 63 + c] : 0.f;
                f[4 + j] = (c < 27) ? xs[r1 * 90 + 63 + c] : 0.f;
            }
            uint32_t h[4], lo[4];
            split2(f[0], f[1], false, h[0], lo[0]);
            split2(f[4], f[5], false, h[1], lo[1]);
            split2(f[2], f[3], false, h[2], lo[2]);
            split2(f[6], f[7], false, h[3], lo[3]);
            uint32_t va = VIEW + (uint32_t)kt * 1024u + (uint32_t)lane * 16u;
            sts128(va,        h[0],  h[1],  h[2],  h[3]);
            sts128(va + 512u, lo[0], lo[1], lo[2], lo[3]);
        }
    }
    // all xs reads done before L0's epilogue overwrites ACT; last CTA-wide sync
    __syncthreads();

    float d0 = 0.f, d1 = 0.f;
    float fin[4] = {0.f, 0.f, 0.f, 0.f};
    const unsigned char* wb = g_wbuf;

    // ---- 9 layers, warps free-running (no CTA barriers) ----
    run_layer<4, 16, true, false, true>((const uint4*)(wb + 0),      POS, 4, 0,   ACT, d0, d1, fin, lane);
    run_layer<8, 16, true, false, true>((const uint4*)(wb + 32768),  ACT, 8, 0,   ACT, d0, d1, fin, lane);
    run_layer<8, 16, true, false, true>((const uint4*)(wb + 98304),  ACT, 8, 0,   ACT, d0, d1, fin, lane);
    run_layer<12,16, true, false, true>((const uint4*)(wb + 163840), POS, 4, ACT, ACT, d0, d1, fin, lane);
    run_layer<8, 16, true, false, true>((const uint4*)(wb + 262144), ACT, 8, 0,   ACT, d0, d1, fin, lane);
    run_layer<8, 16, true, false, true>((const uint4*)(wb + 327680), ACT, 8, 0,   ACT, d0, d1, fin, lane);
    run_layer<8, 17, false, true, true>((const uint4*)(wb + 393216), ACT, 8, 0,   ACT, d0, d1, fin, lane);
    run_layer<10,16, true, false, true>((const uint4*)(wb + 462848), VIEW,2, ACT, ACT, d0, d1, fin, lane);
    run_layer<8, 1, false, false,false>((const uint4*)(wb + 544768), ACT, 8, 0,   ACT, d0, d1, fin, lane);

    // ---- epilogue: gather rgb+density per row via warp-private scratch.
    // Use THIS warp's own POS slot (only read by this warp, and only at L0/L3
    // which this warp has already passed) — safe without any CTA sync.
    float* scr = reinterpret_cast<float*>(smem_raw + S_POS + warp * 4096);
    __syncwarp();
    if (tig == 0) {
        scr[g * 4 + 0] = fin[0];          // r (col 0), row g
        scr[g * 4 + 1] = fin[1];          // g (col 1)
        scr[(g + 8) * 4 + 0] = fin[2];    // row g+8
        scr[(g + 8) * 4 + 1] = fin[3];
        scr[g * 4 + 3] = d0;              // density
        scr[(g + 8) * 4 + 3] = d1;
    } else if (tig == 1) {
        scr[g * 4 + 2] = fin[0];          // b (col 2), row g
        scr[(g + 8) * 4 + 2] = fin[2];    // row g+8
    }
    __syncwarp();
    if (lane < 16) {
        float4 o = *reinterpret_cast<float4*>(scr + lane * 4);
        reinterpret_cast<float4*>(out)[(size_t)blockIdx.x * 128 + warp * 16 + lane] = o;
    }
}

// ---------------------------------------------------------------------------
extern "C" void kernel_launch(void* const* d_in, const int* in_sizes, int n_in,
                              void* d_out, int out_size) {
    const float* x = (const float*)d_in[0];
    WPtrs wp;
    for (int i = 0; i < 9; i++) wp.w[i] = (const float*)d_in[1 + i];

    cudaFuncSetAttribute(nerf_main, cudaFuncAttributeMaxDynamicSharedMemorySize, SMEM_ALLOC);

    nerf_prep<<<134, 256>>>(wp);                  // 134*256 = 34304 frag threads
    nerf_main<<<8192, 256, SMEM_ALLOC>>>(x, (float*)d_out);
}